// round 1
// baseline (speedup 1.0000x reference)
#include <cuda_runtime.h>
#include <math.h>

// ---------------- problem constants ----------------
#define BB 2
#define HH 64
#define WW 64
#define LL 4096            // H*W
#define DM 128             // d_model
#define DI 256             // d_inner
#define NS 16              // d_state
#define DTR 8              // dt_rank
#define KK 4               // directions
#define TOK (BB*LL)        // 8192 tokens
#define SZ  (TOK*DI)       // 2,097,152 per (token,channel) plane

// ---------------- scratch (device globals; no cudaMalloc allowed) ----------------
__device__ float g_xi   [SZ];            // (b,l,256)  conv input (pre-silu branch xi)
__device__ float g_z    [SZ];            // (b,l,256)  silu(z)
__device__ float g_xc   [SZ];            // (b,l,256)  conv output, silu'd
__device__ float g_xdbl [TOK*KK*40];     // (b,k,l,40) : [0:8) dt_r, [8:24) B, [24:40) C
__device__ float g_delta[TOK*KK*DI];     // (b,k,l,256) softplus(dt + bias)
__device__ float g_y4   [KK][SZ];        // per-direction merged y (token-major)
__device__ float g_yln  [SZ];            // LN * z result

// direction map: scan position t -> token index (gather map == merge map)
__device__ __forceinline__ int mapk(int k, int t) {
    if (k == 0) return t;
    if (k == 1) return ((t & 63) << 6) | (t >> 6);
    if (k == 2) return 4095 - t;
    int s = 4095 - t;
    return ((s & 63) << 6) | (s >> 6);
}

// ---------------- generic NT GEMM: C[m,n] = dot(A[m,:], Bw[n,:]) ----------------
// MODE 0: in_proj  (N=512, K=128): n<256 -> g_xi ; n>=256 -> silu -> g_z
// MODE 1: x_proj   (N=40,  K=256): A rows gathered from g_xc via mapk(blockIdx.z, l)
// MODE 2: out_proj (N=128, K=256): plain store to out0
#define BM 64
#define BN 64
#define BKQ 16

template <int MODE>
__global__ void gemm_nt(const float* __restrict__ A,
                        const float* __restrict__ Bw,
                        float* __restrict__ out0,
                        float* __restrict__ out1,
                        int M, int N, int Kd)
{
    __shared__ float As[BKQ][BM + 4];
    __shared__ float Bs[BKQ][BN + 4];
    const int tid  = threadIdx.x;       // 256 threads
    const int tcol = tid & 15;
    const int trow = tid >> 4;
    const int m0 = blockIdx.x * BM;
    const int n0 = blockIdx.y * BN;
    const int kdir = blockIdx.z;

    float acc[4][4];
#pragma unroll
    for (int i = 0; i < 4; i++)
#pragma unroll
        for (int j = 0; j < 4; j++) acc[i][j] = 0.f;

    for (int k0 = 0; k0 < Kd; k0 += BKQ) {
#pragma unroll
        for (int i = 0; i < 4; i++) {
            int idx = tid + i * 256;
            int mm = idx >> 4;
            int kq = idx & 15;
            const float* arow;
            if (MODE == 1) {
                int m = m0 + mm;
                int b = m >> 12, l = m & 4095;
                int tokn = mapk(kdir, l);
                arow = A + ((size_t)((b << 12) + tokn)) * DI;
            } else {
                arow = A + (size_t)(m0 + mm) * Kd;
            }
            As[kq][mm] = arow[k0 + kq];
        }
#pragma unroll
        for (int i = 0; i < 4; i++) {
            int idx = tid + i * 256;
            int nn = idx >> 4;
            int kq = idx & 15;
            float v = 0.f;
            if (MODE != 1 || (n0 + nn) < N)
                v = Bw[(size_t)(n0 + nn) * Kd + k0 + kq];
            Bs[kq][nn] = v;
        }
        __syncthreads();
#pragma unroll
        for (int kq = 0; kq < BKQ; kq++) {
            float ra[4], rb[4];
#pragma unroll
            for (int i = 0; i < 4; i++) ra[i] = As[kq][trow * 4 + i];
#pragma unroll
            for (int j = 0; j < 4; j++) rb[j] = Bs[kq][tcol * 4 + j];
#pragma unroll
            for (int i = 0; i < 4; i++)
#pragma unroll
                for (int j = 0; j < 4; j++)
                    acc[i][j] = fmaf(ra[i], rb[j], acc[i][j]);
        }
        __syncthreads();
    }

#pragma unroll
    for (int i = 0; i < 4; i++) {
#pragma unroll
        for (int j = 0; j < 4; j++) {
            int m = m0 + trow * 4 + i;
            int n = n0 + tcol * 4 + j;
            float v = acc[i][j];
            if (MODE == 0) {
                if (n < DI) out0[(size_t)m * DI + n] = v;
                else        out1[(size_t)m * DI + (n - DI)] = v / (1.f + __expf(-v));
            } else if (MODE == 1) {
                if (n < 40) {
                    int b = m >> 12, l = m & 4095;
                    out0[((size_t)(((b * 4 + kdir) << 12) + l)) * 40 + n] = v;
                }
            } else {
                out0[(size_t)m * DM + n] = v;
            }
        }
    }
}

// ---------------- depthwise 3x3 conv (SAME) + bias + silu, channel-last ----------------
__global__ void conv_silu_kernel(const float* __restrict__ xi,
                                 const float* __restrict__ cw,
                                 const float* __restrict__ cb,
                                 float* __restrict__ xc)
{
    int idx = blockIdx.x * blockDim.x + threadIdx.x;   // over BB*LL*DI = 2M
    if (idx >= SZ) return;
    int d = idx & 255;
    int pix = (idx >> 8) & 4095;
    int b = idx >> 20;
    int h = pix >> 6, w = pix & 63;
    float acc = cb[d];
#pragma unroll
    for (int ky = 0; ky < 3; ky++) {
        int hh = h + ky - 1;
        if ((unsigned)hh >= 64u) continue;
#pragma unroll
        for (int kx = 0; kx < 3; kx++) {
            int ww = w + kx - 1;
            if ((unsigned)ww >= 64u) continue;
            acc = fmaf(xi[((size_t)((b << 12) + (hh << 6) + ww)) * DI + d],
                       cw[d * 9 + ky * 3 + kx], acc);
        }
    }
    xc[idx] = acc / (1.f + __expf(-acc));   // silu
}

// ---------------- dt projection + softplus -> delta ----------------
__global__ void delta_kernel(const float* __restrict__ xdbl,
                             const float* __restrict__ dtw,
                             const float* __restrict__ dtb,
                             float* __restrict__ delta)
{
    size_t idx = (size_t)blockIdx.x * blockDim.x + threadIdx.x;  // BB*KK*LL*DI = 8.4M
    if (idx >= (size_t)TOK * KK * DI) return;
    int d = (int)(idx & 255);
    size_t bkl = idx >> 8;
    int k = (int)((bkl >> 12) & 3);
    const float* xr = xdbl + bkl * 40;
    const float* wr = dtw + (size_t)(k * DI + d) * DTR;
    float s = dtb[k * DI + d];
#pragma unroll
    for (int r = 0; r < DTR; r++) s = fmaf(wr[r], xr[r], s);
    delta[idx] = (s > 20.f) ? s : log1pf(__expf(s));
}

// ---------------- selective scan: half-warp per (b,k,d), lane = state n ----------------
__global__ void scan_kernel(const float* __restrict__ delta,
                            const float* __restrict__ xc,
                            const float* __restrict__ xdbl,
                            const float* __restrict__ A_logs,
                            const float* __restrict__ Ds,
                            float* __restrict__ y4)
{
    int lane = threadIdx.x & 31;
    int warp = threadIdx.x >> 5;
    int scan = blockIdx.x * 8 + warp * 2 + (lane >> 4);  // 0..2047
    int n = lane & 15;
    int d = scan & 255;
    int k = (scan >> 8) & 3;
    int b = scan >> 10;

    const float An = -__expf(A_logs[((size_t)((k << 8) + d)) * NS + n]);
    const float Dk = Ds[(k << 8) + d];

    const float* dbase = delta + ((size_t)(b * 4 + k) << 12) * DI + d;  // + t*256
    const float* xdb   = xdbl  + ((size_t)(b * 4 + k) << 12) * 40;      // + t*40
    const float* xcb   = xc    + ((size_t)b << 12) * DI + d;            // + tok*256
    float*       yb    = y4 + (size_t)k * SZ + ((size_t)b << 12) * DI + d;

    float h = 0.f;
    for (int t = 0; t < LL; t++) {
        int tokn = mapk(k, t);
        float dl = __ldg(dbase + (size_t)t * DI);
        float u  = __ldg(xcb + (size_t)tokn * DI);
        float Bn = __ldg(xdb + (size_t)t * 40 + 8 + n);
        float Cn = __ldg(xdb + (size_t)t * 40 + 24 + n);
        float dA = __expf(dl * An);
        h = fmaf(dA, h, dl * u * Bn);
        float v = h * Cn;
        v += __shfl_xor_sync(0xffffffffu, v, 8);
        v += __shfl_xor_sync(0xffffffffu, v, 4);
        v += __shfl_xor_sync(0xffffffffu, v, 2);
        v += __shfl_xor_sync(0xffffffffu, v, 1);
        if (n == 0) yb[(size_t)tokn * DI] = v + Dk * u;
    }
}

// ---------------- merge 4 dirs + LayerNorm + *z ----------------
__global__ void ln_kernel(const float* __restrict__ y4,
                          const float* __restrict__ lnw,
                          const float* __restrict__ lnb,
                          const float* __restrict__ z,
                          float* __restrict__ yln)
{
    int warp = threadIdx.x >> 5, lane = threadIdx.x & 31;
    int tokn = blockIdx.x * 8 + warp;            // 0..8191
    size_t base = (size_t)tokn * DI;
    float vals[8];
    float s = 0.f, s2 = 0.f;
#pragma unroll
    for (int j = 0; j < 8; j++) {
        int d = lane + j * 32;
        float v = y4[0 * (size_t)SZ + base + d] + y4[1 * (size_t)SZ + base + d]
                + y4[2 * (size_t)SZ + base + d] + y4[3 * (size_t)SZ + base + d];
        vals[j] = v;
        s += v;
        s2 = fmaf(v, v, s2);
    }
#pragma unroll
    for (int o = 16; o > 0; o >>= 1) {
        s  += __shfl_xor_sync(0xffffffffu, s, o);
        s2 += __shfl_xor_sync(0xffffffffu, s2, o);
    }
    float mean = s * (1.f / DI);
    float var = s2 * (1.f / DI) - mean * mean;
    float inv = rsqrtf(var + 1e-5f);
#pragma unroll
    for (int j = 0; j < 8; j++) {
        int d = lane + j * 32;
        float v = (vals[j] - mean) * inv * lnw[d] + lnb[d];
        yln[base + d] = v * z[base + d];
    }
}

// ---------------- launch ----------------
extern "C" void kernel_launch(void* const* d_in, const int* in_sizes, int n_in,
                              void* d_out, int out_size)
{
    const float* x       = (const float*)d_in[0];   // (B,H,W,128)
    const float* w_in    = (const float*)d_in[1];   // (512,128)
    const float* conv_w  = (const float*)d_in[2];   // (256,1,3,3)
    const float* conv_b  = (const float*)d_in[3];   // (256)
    const float* x_projw = (const float*)d_in[4];   // (4,40,256)
    const float* dt_w    = (const float*)d_in[5];   // (4,256,8)
    const float* dt_b    = (const float*)d_in[6];   // (4,256)
    const float* A_logs  = (const float*)d_in[7];   // (1024,16)
    const float* Ds      = (const float*)d_in[8];   // (1024)
    const float* ln_w    = (const float*)d_in[9];   // (256)
    const float* ln_b    = (const float*)d_in[10];  // (256)
    const float* w_out   = (const float*)d_in[11];  // (128,256)
    float* out = (float*)d_out;

    float *xi, *z, *xc, *xdbl, *delta, *y4, *yln;
    cudaGetSymbolAddress((void**)&xi,    g_xi);
    cudaGetSymbolAddress((void**)&z,     g_z);
    cudaGetSymbolAddress((void**)&xc,    g_xc);
    cudaGetSymbolAddress((void**)&xdbl,  g_xdbl);
    cudaGetSymbolAddress((void**)&delta, g_delta);
    cudaGetSymbolAddress((void**)&y4,    g_y4);
    cudaGetSymbolAddress((void**)&yln,   g_yln);

    // 1) in_proj (+ split + silu z)
    gemm_nt<0><<<dim3(TOK / BM, (2 * DI) / BN, 1), 256>>>(x, w_in, xi, z, TOK, 2 * DI, DM);
    // 2) depthwise conv + silu
    conv_silu_kernel<<<(SZ + 255) / 256, 256>>>(xi, conv_w, conv_b, xc);
    // 3) x_proj per direction (gathered A)
    gemm_nt<1><<<dim3(TOK / BM, 1, KK), 256>>>(xc, x_projw, xdbl, nullptr, TOK, 40, DI);
    // 4) dt projection + softplus
    delta_kernel<<<(TOK * KK * DI + 255) / 256, 256>>>(xdbl, dt_w, dt_b, delta);
    // 5) selective scan (writes merged-coordinate per-direction buffers)
    scan_kernel<<<(BB * KK * DI) / 8, 128>>>(delta, xc, xdbl, A_logs, Ds, y4);
    // 6) merge + LN + *z
    ln_kernel<<<TOK / 8, 256>>>(y4, ln_w, ln_b, z, yln);
    // 7) out_proj
    gemm_nt<2><<<dim3(TOK / BM, DM / BN, 1), 256>>>(yln, w_out, out, nullptr, TOK, DM, DI);

    (void)in_sizes; (void)n_in; (void)out_size;
}